// round 15
// baseline (speedup 1.0000x reference)
#include <cuda_runtime.h>
#include <cuda_bf16.h>
#include <cuda_fp16.h>
#include <math.h>
#include <cstdint>

// BlockGCN round 15: mma.sync f16 GEMM (M128xN64 CTA, 3 CTA/SM), residual in G,
// 3-stage cp.async, smem-tiled transpose. out = relu(G_aug @ X + bias).

#define NK 3
#define NH 8
#define NV 23
#define NVP 24
#define CG 16
#define NT 256
#define NN 32
#define NC 128

#define OWP 384
#define CVP 384
#define KCH 64
#define NCHUNK 6
#define MROWS 128
#define TN2 64            // t per CTA
#define THREADS 256

// ---------------- device globals ----------------
__device__ float g_bna[NK][NH][NV][NVP];
__device__ float g_ws[NK][NH][CG][CG];
__device__ float g_bias[NC];
__device__ __align__(16) __half g_G1[NH][OWP][CVP];
__device__ __align__(16) __half g_X16[(size_t)NN * NH * NT * CVP];

__device__ __forceinline__ uint32_t smem_u32(const void* p) {
    uint32_t a;
    asm("{ .reg .u64 t; cvta.to.shared.u64 t, %1; cvt.u32.u64 %0, t; }" : "=r"(a) : "l"(p));
    return a;
}
__device__ __forceinline__ void cp16(uint32_t dst, const void* src) {
    asm volatile("cp.async.cg.shared.global [%0], [%1], 16;" :: "r"(dst), "l"(src));
}
#define CP_COMMIT()  asm volatile("cp.async.commit_group;" ::: "memory")
#define CP_WAIT(n)   asm volatile("cp.async.wait_group %0;" :: "n"(n) : "memory")

#define LDMX4(r0, r1, r2, r3, addr) \
    asm volatile("ldmatrix.sync.aligned.m8n8.x4.shared.b16 {%0,%1,%2,%3}, [%4];" \
        : "=r"(r0), "=r"(r1), "=r"(r2), "=r"(r3) : "r"(addr))

#define MMA16816(c0, c1, c2, c3, a0, a1, a2, a3, b0, b1) \
    asm volatile("mma.sync.aligned.m16n8k16.row.col.f32.f16.f16.f32 " \
        "{%0,%1,%2,%3}, {%4,%5,%6,%7}, {%8,%9}, {%0,%1,%2,%3};" \
        : "+f"(c0), "+f"(c1), "+f"(c2), "+f"(c3) \
        : "r"(a0), "r"(a1), "r"(a2), "r"(a3), "r"(b0), "r"(b1))

#define SWZ16(chunk, row) ((chunk) ^ ((row) & 7))

// ---------------- precompute 1 ----------------
__global__ void precompute_kernel(const float* __restrict__ emb,
                                  const float* __restrict__ A,
                                  const float* __restrict__ conv_w,
                                  const float* __restrict__ conv_b,
                                  const float* __restrict__ gamma,
                                  const float* __restrict__ beta,
                                  const float* __restrict__ mean,
                                  const float* __restrict__ var,
                                  const int*   __restrict__ hop,
                                  int n_hop)
{
    int b = blockIdx.x;
    int tid = threadIdx.x;
    if (b < NK * NH) {
        int k = b / NH, h = b % NH;
        int w = tid;
        if (w < NV) {
            float Bc[NV], Ac[NV];
            float sB = 0.f, sA = 0.f;
            #pragma unroll
            for (int v = 0; v < NV; v++) {
                float bb = emb[(k * NH + h) * n_hop + hop[v * NV + w]];
                float aa = A[((k * NH + h) * NV + v) * NV + w];
                Bc[v] = bb; Ac[v] = aa;
                sB += bb * bb; sA += aa * aa;
            }
            float iB = 1.f / (sqrtf(sB) + 1e-4f);
            float iA = 1.f / (sqrtf(sA) + 1e-4f);
            #pragma unroll
            for (int v = 0; v < NV; v++)
                g_bna[k][h][w][v] = Bc[v] * iB + Ac[v] * iA;
            g_bna[k][h][w][NV] = 0.f;
        }
    } else {
        for (int idx = tid; idx < NK * NC * CG; idx += blockDim.x) {
            int row = idx / CG, c = idx % CG;
            int k = row / NC, och = row % NC;
            float inv = gamma[och] * rsqrtf(var[och] + 1e-5f);
            int h = och / CG, o = och % CG;
            g_ws[k][h][o][c] = conv_w[row * CG + c] * inv;
        }
        for (int och = tid; och < NC; och += blockDim.x) {
            float inv = gamma[och] * rsqrtf(var[och] + 1e-5f);
            float sb = conv_b[och] + conv_b[NC + och] + conv_b[2 * NC + och];
            g_bias[och] = sb * inv + beta[och] - mean[och] * inv;
        }
    }
}

// ---------------- precompute 2: combined operator + residual identity ----------------
__global__ void build_G_kernel()
{
    int ow = blockIdx.x;
    int h  = blockIdx.y;
    int cv = threadIdx.x;
    int o = ow / NVP, w = ow % NVP;
    int c = cv / NVP, v = cv % NVP;
    float G = 0.f;
    if (w < NV && v < NV) {
        #pragma unroll
        for (int k = 0; k < NK; k++)
            G += g_ws[k][h][o][c] * g_bna[k][h][w][v];
        if (o == c && w == v) G += 1.0f;
    }
    g_G1[h][ow][cv] = __float2half(G);
}

// ---------------- transpose: x -> fp16 [n][h][t][cv], smem-tiled ----------------
#define TT 32    // t per tile
__global__ __launch_bounds__(256)
void transpose_kernel(const float* __restrict__ x)
{
    __shared__ __half tile[TT][CVP + 8];   // stride 392 halfs = 784B (16B-mult)
    const int h = blockIdx.x & 7;
    const int n = blockIdx.x >> 3;
    const int tid = threadIdx.x;

    for (int tc = 0; tc < NT / TT; tc++) {
        const int t0 = tc * TT;
        // read 16 c-planes, each 736 contiguous floats, via float4
        #pragma unroll 1
        for (int c = 0; c < CG; c++) {
            const float4* src = (const float4*)(x +
                (((size_t)(n * NC + h * CG + c)) * NT + t0) * NV);
            for (int i = tid; i < TT * NV / 4; i += 256) {   // 184
                float4 f = src[i];
                int lin = i * 4;
                tile[lin / NV][c * NVP + lin % NV] = __float2half(f.x);  lin++;
                tile[lin / NV][c * NVP + lin % NV] = __float2half(f.y);  lin++;
                tile[lin / NV][c * NVP + lin % NV] = __float2half(f.z);  lin++;
                tile[lin / NV][c * NVP + lin % NV] = __float2half(f.w);
            }
            if (tid < TT) tile[tid][c * NVP + NV] = __float2half(0.f);
        }
        __syncthreads();
        // coalesced uint4 writes
        __half* dst = g_X16 + ((size_t)(n * NH + h) * NT + t0) * CVP;
        for (int i = tid; i < TT * (CVP / 8); i += 256) {    // 1536
            int row = i / (CVP / 8), u = i % (CVP / 8);
            ((uint4*)(dst + (size_t)row * CVP))[u] = *(const uint4*)&tile[row][u * 8];
        }
        __syncthreads();
    }
}

// ---------------- main GEMM kernel ----------------
// dynamic smem 72KB: 3 stages x {A:16KB, B:8KB}; epilogue reuses [0, 16.6KB)
#define STAGE_BYTES 24576
#define SM_TOTAL (3 * STAGE_BYTES)

__global__ __launch_bounds__(THREADS, 3)
void blockgcn_gemm_kernel(float* __restrict__ out)
{
    extern __shared__ __align__(16) char sm[];
    const uint32_t smb = smem_u32(sm);
    const int tid = threadIdx.x;
    const int wid = tid >> 5;
    const int lane = tid & 31;
    const int mw = wid & 1;          // M warp (64 rows)
    const int nw = wid >> 1;         // N warp (16 t)

    const int mtile = blockIdx.x >> 2;       // 0..2
    const int tq    = blockIdx.x & 3;        // 0..3
    const int n     = blockIdx.y;
    const int h     = blockIdx.z;
    const int m0    = mtile * MROWS;
    const int t0    = tq * TN2;

    const __half* Ab = &g_G1[h][m0][0];
    const __half* Bb = g_X16 + ((size_t)(n * NH + h) * NT + t0) * CVP;

    float acc[4][2][4];
    #pragma unroll
    for (int i = 0; i < 4; i++)
        #pragma unroll
        for (int j = 0; j < 2; j++)
            #pragma unroll
            for (int r = 0; r < 4; r++) acc[i][j][r] = 0.f;

    const int rA = (lane & 7) + ((lane >> 3) & 1) * 8;
    const int cA = (lane >> 4);
    const int rB = (lane & 7) + (lane >> 4) * 8;
    const int cB = (lane >> 3) & 1;

    auto stage = [&](int kc, int buf) {
        const __half* As = Ab + kc * KCH;
        const __half* Bs = Bb + kc * KCH;
        #pragma unroll
        for (int i = tid; i < 1536; i += THREADS) {   // A:1024, B:512
            int isB = (i >= 1024);
            int j   = isB ? (i - 1024) : i;
            int row = j >> 3, u = j & 7;
            uint32_t dst = smb + buf * STAGE_BYTES + isB * 16384
                         + row * 128 + SWZ16(u, row) * 16;
            const __half* src = (isB ? Bs : As) + (size_t)row * CVP + u * 8;
            cp16(dst, src);
        }
        CP_COMMIT();
    };

    stage(0, 0);
    stage(1, 1);

    for (int kc = 0; kc < NCHUNK; kc++) {
        __syncthreads();
        if (kc + 2 < NCHUNK) { stage(kc + 2, (kc + 2) % 3); CP_WAIT(2); }
        else if (kc + 2 == NCHUNK) { CP_WAIT(1); }
        else { CP_WAIT(0); }
        __syncthreads();

        const uint32_t abase = smb + (kc % 3) * STAGE_BYTES;
        const uint32_t bbase = abase + 16384;

        #pragma unroll
        for (int ks = 0; ks < 4; ks++) {
            uint32_t b[4];
            {
                int rowB = nw * 16 + rB;
                uint32_t ad = bbase + rowB * 128 + SWZ16(ks * 2 + cB, rowB) * 16;
                LDMX4(b[0], b[1], b[2], b[3], ad);
            }
            #pragma unroll
            for (int mf = 0; mf < 4; mf++) {
                int rowA = mw * 64 + mf * 16 + rA;
                uint32_t ad = abase + rowA * 128 + SWZ16(ks * 2 + cA, rowA) * 16;
                uint32_t a0, a1, a2, a3;
                LDMX4(a0, a1, a2, a3, ad);
                #pragma unroll
                for (int nf = 0; nf < 2; nf++) {
                    MMA16816(acc[mf][nf][0], acc[mf][nf][1],
                             acc[mf][nf][2], acc[mf][nf][3],
                             a0, a1, a2, a3, b[nf * 2], b[nf * 2 + 1]);
                }
            }
        }
    }

    // ---- epilogue via smem transpose (residual already in Y) ----
    float (*ep)[TN2 + 1] = (float (*)[TN2 + 1])sm;
    const int g = lane >> 2, tig = lane & 3;
    for (int mh = 0; mh < 2; mh++) {
        __syncthreads();
        if (mw == mh) {
            #pragma unroll
            for (int mf = 0; mf < 4; mf++) {
                #pragma unroll
                for (int nf = 0; nf < 2; nf++) {
                    int row = mf * 16 + g;
                    int col = nw * 16 + nf * 8 + tig * 2;
                    ep[row][col]         = acc[mf][nf][0];
                    ep[row][col + 1]     = acc[mf][nf][1];
                    ep[row + 8][col]     = acc[mf][nf][2];
                    ep[row + 8][col + 1] = acc[mf][nf][3];
                }
            }
        }
        __syncthreads();
        for (int idx = tid; idx < 64 * TN2; idx += THREADS) {
            int mr = idx & 63;
            int tt = idx >> 6;
            int m  = m0 + mh * 64 + mr;
            int o  = m / NVP, w = m - o * NVP;
            if (w < NV) {
                int och = h * CG + o;
                size_t ga = ((size_t)(n * NC + och)) * (NT * NV) + (size_t)(t0 + tt) * NV + w;
                out[ga] = fmaxf(ep[mr][tt] + g_bias[och], 0.f);
            }
        }
    }
}

extern "C" void kernel_launch(void* const* d_in, const int* in_sizes, int n_in,
                              void* d_out, int out_size)
{
    const float* x      = (const float*)d_in[0];
    const float* emb    = (const float*)d_in[1];
    const float* A      = (const float*)d_in[2];
    const float* conv_w = (const float*)d_in[3];
    const float* conv_b = (const float*)d_in[4];
    const float* gamma  = (const float*)d_in[5];
    const float* beta   = (const float*)d_in[6];
    const float* mean   = (const float*)d_in[7];
    const float* var    = (const float*)d_in[8];
    const int*   hop    = (const int*)d_in[9];

    int n_hop = in_sizes[1] / (NK * NH);

    static bool attr_set = false;
    if (!attr_set) {
        cudaFuncSetAttribute(blockgcn_gemm_kernel,
                             cudaFuncAttributeMaxDynamicSharedMemorySize, SM_TOTAL);
        attr_set = true;
    }

    precompute_kernel<<<NK * NH + 1, 256>>>(emb, A, conv_w, conv_b,
                                            gamma, beta, mean, var, hop, n_hop);
    build_G_kernel<<<dim3(OWP, NH), CVP>>>();
    transpose_kernel<<<NN * NH, 256>>>(x);

    dim3 grid(12, NN, NH);   // (mtile*4 + tq, n, h)
    blockgcn_gemm_kernel<<<grid, THREADS, SM_TOTAL>>>((float*)d_out);
}

// round 16
// speedup vs baseline: 1.4130x; 1.4130x over previous
#include <cuda_runtime.h>
#include <cuda_bf16.h>
#include <cuda_fp16.h>
#include <math.h>
#include <cstdint>

// BlockGCN round 16: R14 GEMM (M128xN128, 2 CTA/SM, residual fused in G,
// 3-stage cp.async) + parallel smem-tiled transpose. out = relu(G_aug@X + bias).

#define NK 3
#define NH 8
#define NV 23
#define NVP 24
#define CG 16
#define NT 256
#define NN 32
#define NC 128

#define OWP 384
#define CVP 384
#define KCH 64
#define NCHUNK 6
#define MROWS 128
#define TN 128
#define THREADS 256

// ---------------- device globals ----------------
__device__ float g_bna[NK][NH][NV][NVP];
__device__ float g_ws[NK][NH][CG][CG];
__device__ float g_bias[NC];
__device__ __align__(16) __half g_G1[NH][OWP][CVP];
__device__ __align__(16) __half g_X16[(size_t)NN * NH * NT * CVP];

__device__ __forceinline__ uint32_t smem_u32(const void* p) {
    uint32_t a;
    asm("{ .reg .u64 t; cvta.to.shared.u64 t, %1; cvt.u32.u64 %0, t; }" : "=r"(a) : "l"(p));
    return a;
}
__device__ __forceinline__ void cp16(uint32_t dst, const void* src) {
    asm volatile("cp.async.cg.shared.global [%0], [%1], 16;" :: "r"(dst), "l"(src));
}
#define CP_COMMIT()  asm volatile("cp.async.commit_group;" ::: "memory")
#define CP_WAIT(n)   asm volatile("cp.async.wait_group %0;" :: "n"(n) : "memory")

#define LDMX4(r0, r1, r2, r3, addr) \
    asm volatile("ldmatrix.sync.aligned.m8n8.x4.shared.b16 {%0,%1,%2,%3}, [%4];" \
        : "=r"(r0), "=r"(r1), "=r"(r2), "=r"(r3) : "r"(addr))

#define MMA16816(c0, c1, c2, c3, a0, a1, a2, a3, b0, b1) \
    asm volatile("mma.sync.aligned.m16n8k16.row.col.f32.f16.f16.f32 " \
        "{%0,%1,%2,%3}, {%4,%5,%6,%7}, {%8,%9}, {%0,%1,%2,%3};" \
        : "+f"(c0), "+f"(c1), "+f"(c2), "+f"(c3) \
        : "r"(a0), "r"(a1), "r"(a2), "r"(a3), "r"(b0), "r"(b1))

#define SWZ16(chunk, row) ((chunk) ^ ((row) & 7))

// ---------------- precompute 1 ----------------
__global__ void precompute_kernel(const float* __restrict__ emb,
                                  const float* __restrict__ A,
                                  const float* __restrict__ conv_w,
                                  const float* __restrict__ conv_b,
                                  const float* __restrict__ gamma,
                                  const float* __restrict__ beta,
                                  const float* __restrict__ mean,
                                  const float* __restrict__ var,
                                  const int*   __restrict__ hop,
                                  int n_hop)
{
    int b = blockIdx.x;
    int tid = threadIdx.x;
    if (b < NK * NH) {
        int k = b / NH, h = b % NH;
        int w = tid;
        if (w < NV) {
            float Bc[NV], Ac[NV];
            float sB = 0.f, sA = 0.f;
            #pragma unroll
            for (int v = 0; v < NV; v++) {
                float bb = emb[(k * NH + h) * n_hop + hop[v * NV + w]];
                float aa = A[((k * NH + h) * NV + v) * NV + w];
                Bc[v] = bb; Ac[v] = aa;
                sB += bb * bb; sA += aa * aa;
            }
            float iB = 1.f / (sqrtf(sB) + 1e-4f);
            float iA = 1.f / (sqrtf(sA) + 1e-4f);
            #pragma unroll
            for (int v = 0; v < NV; v++)
                g_bna[k][h][w][v] = Bc[v] * iB + Ac[v] * iA;
            g_bna[k][h][w][NV] = 0.f;
        }
    } else {
        for (int idx = tid; idx < NK * NC * CG; idx += blockDim.x) {
            int row = idx / CG, c = idx % CG;
            int k = row / NC, och = row % NC;
            float inv = gamma[och] * rsqrtf(var[och] + 1e-5f);
            int h = och / CG, o = och % CG;
            g_ws[k][h][o][c] = conv_w[row * CG + c] * inv;
        }
        for (int och = tid; och < NC; och += blockDim.x) {
            float inv = gamma[och] * rsqrtf(var[och] + 1e-5f);
            float sb = conv_b[och] + conv_b[NC + och] + conv_b[2 * NC + och];
            g_bias[och] = sb * inv + beta[och] - mean[och] * inv;
        }
    }
}

// ---------------- precompute 2: combined operator + residual identity ----------------
__global__ void build_G_kernel()
{
    int ow = blockIdx.x;
    int h  = blockIdx.y;
    int cv = threadIdx.x;
    int o = ow / NVP, w = ow % NVP;
    int c = cv / NVP, v = cv % NVP;
    float G = 0.f;
    if (w < NV && v < NV) {
        #pragma unroll
        for (int k = 0; k < NK; k++)
            G += g_ws[k][h][o][c] * g_bna[k][h][w][v];
        if (o == c && w == v) G += 1.0f;   // fused residual
    }
    g_G1[h][ow][cv] = __float2half(G);
}

// ---------------- transpose: x -> fp16 [n][h][t][cv], parallel smem tile ----------------
#define TT 32
__global__ __launch_bounds__(256)
void transpose_kernel(const float* __restrict__ x)
{
    __shared__ __half tile[TT][CVP + 8];   // stride 392 halfs
    const int tc  = blockIdx.x & 7;        // t-chunk
    const int h   = (blockIdx.x >> 3) & 7;
    const int n   = blockIdx.x >> 6;
    const int t0  = tc * TT;
    const int tid = threadIdx.x;

    // reads: all 16 c-planes in parallel; each plane = 184 float4 (contiguous)
    for (int i = tid; i < CG * 184; i += 256) {
        int c = i / 184, j = i % 184;
        const float4* src = (const float4*)(x +
            (((size_t)(n * NC + h * CG + c)) * NT + t0) * NV);
        float4 f = src[j];
        int lin = j * 4;
        tile[lin / NV][c * NVP + lin % NV] = __float2half(f.x);  lin++;
        tile[lin / NV][c * NVP + lin % NV] = __float2half(f.y);  lin++;
        tile[lin / NV][c * NVP + lin % NV] = __float2half(f.z);  lin++;
        tile[lin / NV][c * NVP + lin % NV] = __float2half(f.w);
    }
    // zero the v=23 pad column for every (t, c)
    for (int i = tid; i < TT * CG; i += 256)
        tile[i / CG][(i % CG) * NVP + NV] = __float2half(0.f);
    __syncthreads();

    // coalesced uint4 writes
    __half* dst = g_X16 + ((size_t)(n * NH + h) * NT + t0) * CVP;
    for (int i = tid; i < TT * (CVP / 8); i += 256) {
        int row = i / (CVP / 8), u = i % (CVP / 8);
        ((uint4*)(dst + (size_t)row * CVP))[u] = *(const uint4*)&tile[row][u * 8];
    }
}

// ---------------- main GEMM kernel (R14, proven) ----------------
#define SM_TOTAL (3 * 32768)

__global__ __launch_bounds__(THREADS, 2)
void blockgcn_gemm_kernel(float* __restrict__ out)
{
    extern __shared__ __align__(16) char sm[];
    const uint32_t smb = smem_u32(sm);
    const int tid = threadIdx.x;
    const int wid = tid >> 5;
    const int lane = tid & 31;
    const int mw = wid & 1;
    const int nw = wid >> 1;

    const int mtile = blockIdx.x >> 1;
    const int thalf = blockIdx.x & 1;
    const int n     = blockIdx.y;
    const int h     = blockIdx.z;
    const int m0    = mtile * MROWS;
    const int t0    = thalf * TN;

    const __half* Ab = &g_G1[h][m0][0];
    const __half* Bb = g_X16 + ((size_t)(n * NH + h) * NT + t0) * CVP;

    float acc[4][4][4];
    #pragma unroll
    for (int i = 0; i < 4; i++)
        #pragma unroll
        for (int j = 0; j < 4; j++)
            #pragma unroll
            for (int r = 0; r < 4; r++) acc[i][j][r] = 0.f;

    const int rA = (lane & 7) + ((lane >> 3) & 1) * 8;
    const int cA = (lane >> 4);
    const int rB = (lane & 7) + (lane >> 4) * 8;
    const int cB = (lane >> 3) & 1;

    auto stage = [&](int kc, int buf) {
        const __half* As = Ab + kc * KCH;
        const __half* Bs = Bb + kc * KCH;
        #pragma unroll
        for (int i = tid; i < 2048; i += THREADS) {
            int isB = i >> 10, row = (i >> 3) & 127, u = i & 7;
            uint32_t dst = smb + buf * 32768 + isB * 16384
                         + row * 128 + SWZ16(u, row) * 16;
            const __half* src = (isB ? Bs : As) + (size_t)row * CVP + u * 8;
            cp16(dst, src);
        }
        CP_COMMIT();
    };

    stage(0, 0);
    stage(1, 1);

    for (int kc = 0; kc < NCHUNK; kc++) {
        __syncthreads();
        if (kc + 2 < NCHUNK) { stage(kc + 2, (kc + 2) % 3); CP_WAIT(2); }
        else if (kc + 2 == NCHUNK) { CP_WAIT(1); }
        else { CP_WAIT(0); }
        __syncthreads();

        const uint32_t abase = smb + (kc % 3) * 32768;
        const uint32_t bbase = abase + 16384;

        #pragma unroll
        for (int ks = 0; ks < 4; ks++) {
            uint32_t b[2][4];
            #pragma unroll
            for (int nf2 = 0; nf2 < 2; nf2++) {
                int rowB = nw * 32 + nf2 * 16 + rB;
                uint32_t ad = bbase + rowB * 128 + SWZ16(ks * 2 + cB, rowB) * 16;
                LDMX4(b[nf2][0], b[nf2][1], b[nf2][2], b[nf2][3], ad);
            }
            #pragma unroll
            for (int mf = 0; mf < 4; mf++) {
                int rowA = mw * 64 + mf * 16 + rA;
                uint32_t ad = abase + rowA * 128 + SWZ16(ks * 2 + cA, rowA) * 16;
                uint32_t a0, a1, a2, a3;
                LDMX4(a0, a1, a2, a3, ad);
                #pragma unroll
                for (int nf = 0; nf < 4; nf++) {
                    uint32_t bb0 = b[nf >> 1][(nf & 1) * 2];
                    uint32_t bb1 = b[nf >> 1][(nf & 1) * 2 + 1];
                    MMA16816(acc[mf][nf][0], acc[mf][nf][1],
                             acc[mf][nf][2], acc[mf][nf][3],
                             a0, a1, a2, a3, bb0, bb1);
                }
            }
        }
    }

    // ---- epilogue via smem transpose (residual already in Y) ----
    float (*ep)[129] = (float (*)[129])sm;
    const int g = lane >> 2, tig = lane & 3;
    for (int mh = 0; mh < 2; mh++) {
        __syncthreads();
        if (mw == mh) {
            #pragma unroll
            for (int mf = 0; mf < 4; mf++) {
                #pragma unroll
                for (int nf = 0; nf < 4; nf++) {
                    int row = mf * 16 + g;
                    int col = nw * 32 + nf * 8 + tig * 2;
                    ep[row][col]         = acc[mf][nf][0];
                    ep[row][col + 1]     = acc[mf][nf][1];
                    ep[row + 8][col]     = acc[mf][nf][2];
                    ep[row + 8][col + 1] = acc[mf][nf][3];
                }
            }
        }
        __syncthreads();
        for (int idx = tid; idx < 64 * TN; idx += THREADS) {
            int mr = idx & 63;
            int tt = idx >> 6;
            int m  = m0 + mh * 64 + mr;
            int o  = m / NVP, w = m - o * NVP;
            if (w < NV) {
                int och = h * CG + o;
                size_t ga = ((size_t)(n * NC + och)) * (NT * NV) + (size_t)(t0 + tt) * NV + w;
                out[ga] = fmaxf(ep[mr][tt] + g_bias[och], 0.f);
            }
        }
    }
}

extern "C" void kernel_launch(void* const* d_in, const int* in_sizes, int n_in,
                              void* d_out, int out_size)
{
    const float* x      = (const float*)d_in[0];
    const float* emb    = (const float*)d_in[1];
    const float* A      = (const float*)d_in[2];
    const float* conv_w = (const float*)d_in[3];
    const float* conv_b = (const float*)d_in[4];
    const float* gamma  = (const float*)d_in[5];
    const float* beta   = (const float*)d_in[6];
    const float* mean   = (const float*)d_in[7];
    const float* var    = (const float*)d_in[8];
    const int*   hop    = (const int*)d_in[9];

    int n_hop = in_sizes[1] / (NK * NH);

    static bool attr_set = false;
    if (!attr_set) {
        cudaFuncSetAttribute(blockgcn_gemm_kernel,
                             cudaFuncAttributeMaxDynamicSharedMemorySize, SM_TOTAL);
        attr_set = true;
    }

    precompute_kernel<<<NK * NH + 1, 256>>>(emb, A, conv_w, conv_b,
                                            gamma, beta, mean, var, hop, n_hop);
    build_G_kernel<<<dim3(OWP, NH), CVP>>>();
    transpose_kernel<<<NN * NH * 8, 256>>>(x);

    dim3 grid(6, NN, NH);
    blockgcn_gemm_kernel<<<grid, THREADS, SM_TOTAL>>>((float*)d_out);
}